// round 1
// baseline (speedup 1.0000x reference)
#include <cuda_runtime.h>
#include <cuda_bf16.h>

// RetinaFace decode, N = 1e6 priors.
// Inputs (metadata order):
//   d_in[0]: input  float32 [1, N, 16]   (loc4 | cls2 | landm10)
//   d_in[1]: score_threshold float32 [1]
//   d_in[2]: priors float32 [N, 4]
//   d_in[3]: variance float32 [2]
// Output (float32, concatenated flattened tuple):
//   [0      , 4N )  boxes_m      (N,4)
//   [4N     , 5N )  conf_m       (N,)
//   [5N     , 6N )  pred_m       (N,)   == 0 always (2-class decode)
//   [6N     , 22N)  detections   (1,N,16)
//   [22N    , 23N)  keep         (N,)   as 0/1

__global__ __launch_bounds__(256) void retina_decode_kernel(
    const float4* __restrict__ in,      // [N*4] float4 = [N,16] floats
    const float4* __restrict__ priors,  // [N]   float4
    const float* __restrict__ thr,      // [1]
    const float* __restrict__ var,      // [2]
    float* __restrict__ out,
    int N)
{
    int i = blockIdx.x * blockDim.x + threadIdx.x;
    if (i >= N) return;

    const float v0 = var[0];
    const float v1 = var[1];
    const float t  = thr[0];

    float4 a = in[4 * i + 0];  // loc:  cx, cy, w, h deltas
    float4 b = in[4 * i + 1];  // c0, c1, lm0x, lm0y
    float4 c = in[4 * i + 2];  // lm1x, lm1y, lm2x, lm2y
    float4 d = in[4 * i + 3];  // lm3x, lm3y, lm4x, lm4y
    float4 p = priors[i];      // px, py, pw, ph

    // 2-class softmax: conf = max prob; pred==1 iff c1 > c0 (argmax tie -> 0)
    float m  = fmaxf(b.x, b.y);
    float e0 = __expf(b.x - m);
    float e1 = __expf(b.y - m);
    float conf = fmaxf(e0, e1) / (e0 + e1);
    bool  pred1 = (b.y > b.x);
    bool  keep  = pred1 && (conf > t);
    float mf    = keep ? 1.0f : 0.0f;

    // decode box
    float cx = p.x + a.x * v0 * p.z;
    float cy = p.y + a.y * v0 * p.w;
    float w  = p.z * __expf(a.z * v1);
    float h  = p.w * __expf(a.w * v1);
    float x0 = cx - 0.5f * w;
    float y0 = cy - 0.5f * h;
    float x1 = x0 + w;
    float y1 = y0 + h;

    // decode landmarks: l = prior.xy + pt * v0 * prior.wh
    float sx = v0 * p.z, sy = v0 * p.w;
    float l0x = p.x + b.z * sx, l0y = p.y + b.w * sy;
    float l1x = p.x + c.x * sx, l1y = p.y + c.y * sy;
    float l2x = p.x + c.z * sx, l2y = p.y + c.w * sy;
    float l3x = p.x + d.x * sx, l3y = p.y + d.y * sy;
    float l4x = p.x + d.z * sx, l4y = p.y + d.w * sy;

    // mask
    float4 box = make_float4(x0 * mf, y0 * mf, x1 * mf, y1 * mf);
    float confm = conf * mf;

    size_t Ns = (size_t)N;

    // boxes_m [N,4]
    reinterpret_cast<float4*>(out)[i] = box;
    // conf_m [N]
    out[4 * Ns + i] = confm;
    // pred_m [N] -- identically zero for 2-class decode
    out[5 * Ns + i] = 0.0f;
    // detections [N,16] = box4 | conf | pred | landm10
    float4* det = reinterpret_cast<float4*>(out + 6 * Ns) + 4 * (size_t)i;
    det[0] = box;
    det[1] = make_float4(confm, 0.0f, l0x * mf, l0y * mf);
    det[2] = make_float4(l1x * mf, l1y * mf, l2x * mf, l2y * mf);
    det[3] = make_float4(l3x * mf, l3y * mf, l4x * mf, l4y * mf);
    // keep [N]
    out[22 * Ns + i] = mf;
}

extern "C" void kernel_launch(void* const* d_in, const int* in_sizes, int n_in,
                              void* d_out, int out_size)
{
    const float4* in     = (const float4*)d_in[0];
    const float*  thr    = (const float*)d_in[1];
    const float4* priors = (const float4*)d_in[2];
    const float*  var    = (const float*)d_in[3];
    float* out = (float*)d_out;

    int N = in_sizes[2] / 4;  // priors is [N,4]

    int threads = 256;
    int blocks  = (N + threads - 1) / threads;
    retina_decode_kernel<<<blocks, threads>>>(in, priors, thr, var, out, N);
}